// round 1
// baseline (speedup 1.0000x reference)
#include <cuda_runtime.h>

// Double accumulators: [0] = sum of residuals for flow0 (kz=3),
//                      [1] = sum of residuals for flow1 (kz=5).
__device__ double g_acc[2];

__global__ void init_acc_kernel() {
    g_acc[0] = 0.0;
    g_acc[1] = 0.0;
}

// Separable affine-regularization residual.
//   res(pixel) = S2 - (Sa^2 + Sc^2)/D1 - S0^2/D0
// with S* = separable kz-window sums of f, a'*f, c'*f, f^2 over the patch,
// a' = a - (kz-1)/2 centered offsets. This equals p^T (I-P) p = p^T K^T K p,
// and the coordinate grids (affine in patch offsets) contribute exactly zero.
//
// One thread per column, rolling KZ-row register window for the vertical pass,
// double-buffered shared memory for the horizontal pass (1 __syncthreads/row).
template <int KZ, int W, int CHUNK, int ACC>
__global__ __launch_bounds__(W) void residual_kernel(const float* __restrict__ flow) {
    constexpr int HOUT = W - KZ + 1;
    constexpr float m = (KZ - 1) * 0.5f;
    constexpr float invD1 = 12.0f / (float)(KZ * KZ * (KZ * KZ - 1));
    constexpr float invD0 = 1.0f / (float)(KZ * KZ);

    const int plane = blockIdx.x;                    // b*2 + channel, 0..63
    const int i0 = blockIdx.y * CHUNK;               // first output row of chunk
    const int rows = min(CHUNK, HOUT - i0);
    const float* __restrict__ g = flow + (size_t)plane * W * W;
    const int j = threadIdx.x;                       // column

    __shared__ float sV0[2][W];
    __shared__ float sVa[2][W];
    __shared__ float sV2[2][W];

    // Rolling register window: rows i .. i+KZ-1 at column j.
    float r[KZ];
#pragma unroll
    for (int a = 0; a < KZ; ++a) r[a] = g[(i0 + a) * W + j];

    float partial = 0.0f;

    for (int ii = 0; ii < rows; ++ii) {
        // Vertical sums for this column.
        float V0 = 0.0f, Va = 0.0f, V2 = 0.0f;
#pragma unroll
        for (int a = 0; a < KZ; ++a) {
            V0 += r[a];
            Va += ((float)a - m) * r[a];
            V2 += r[a] * r[a];
        }
        const int buf = ii & 1;
        sV0[buf][j] = V0;
        sVa[buf][j] = Va;
        sV2[buf][j] = V2;
        __syncthreads();

        if (j < HOUT) {  // valid output columns (square: WOUT == HOUT)
            float S0 = 0.0f, Sa = 0.0f, Sc = 0.0f, S2 = 0.0f;
#pragma unroll
            for (int c = 0; c < KZ; ++c) {
                const float v0 = sV0[buf][j + c];
                S0 += v0;
                Sc += ((float)c - m) * v0;
                Sa += sVa[buf][j + c];
                S2 += sV2[buf][j + c];
            }
            partial += S2 - (Sa * Sa + Sc * Sc) * invD1 - S0 * S0 * invD0;
        }

        // Roll the register window down one input row.
        if (ii + 1 < rows) {
#pragma unroll
            for (int a = 0; a < KZ - 1; ++a) r[a] = r[a + 1];
            r[KZ - 1] = g[(i0 + ii + KZ) * W + j];
        }
    }

    // Block reduction (double) -> single atomicAdd per block.
    double p = (double)partial;
#pragma unroll
    for (int off = 16; off > 0; off >>= 1)
        p += __shfl_down_sync(0xffffffffu, p, off);

    __shared__ double warpsum[W / 32];
    if ((threadIdx.x & 31) == 0) warpsum[threadIdx.x >> 5] = p;
    __syncthreads();
    if (threadIdx.x == 0) {
        double s = 0.0;
#pragma unroll
        for (int k = 0; k < W / 32; ++k) s += warpsum[k];
        atomicAdd(&g_acc[ACC], s);
    }
}

__global__ void finalize_kernel(float* out) {
    const double n0 = 32.0 * 126.0 * 126.0;  // b * hout * wout for kz=3, W=128
    const double n1 = 32.0 * 252.0 * 252.0;  // b * hout * wout for kz=5, W=256
    out[0] = (float)(g_acc[0] / n0 + g_acc[1] / n1);
}

extern "C" void kernel_launch(void* const* d_in, const int* in_sizes, int n_in,
                              void* d_out, int out_size) {
    const float* flow0 = (const float*)d_in[0];  // (32, 2, 128, 128)
    const float* flow1 = (const float*)d_in[1];  // (32, 2, 256, 256)
    // Defensive: identify by size (flow0 has 32*2*128*128 = 1048576 elems).
    if (n_in >= 2 && in_sizes[0] > in_sizes[1]) {
        const float* t = flow0; flow0 = flow1; flow1 = t;
    }
    float* out = (float*)d_out;

    init_acc_kernel<<<1, 1>>>();

    // kz=3, W=128: HOUT=126, 8 row-chunks of 16 -> 64x8 = 512 blocks of 128 thr.
    residual_kernel<3, 128, 16, 0><<<dim3(64, (126 + 15) / 16), 128>>>(flow0);

    // kz=5, W=256: HOUT=252, 8 row-chunks of 32 -> 64x8 = 512 blocks of 256 thr.
    residual_kernel<5, 256, 32, 1><<<dim3(64, (252 + 31) / 32), 256>>>(flow1);

    finalize_kernel<<<1, 1>>>(out);
}

// round 2
// speedup vs baseline: 1.9767x; 1.9767x over previous
#include <cuda_runtime.h>

__device__ double   g_acc[2];   // [0]=flow0 (kz=3), [1]=flow1 (kz=5)
__device__ unsigned g_cnt = 0;

// Warp-strip separable affine residual.
//   res(pixel) = S2 - (Sa^2 + Sc^2)/D1 - S0^2/D0   ( == p^T K^T K p; the
// coordinate grids are affine in patch offsets and are annihilated by I-P).
// One warp covers W columns (CPT per lane); vertical kz-window sums V0/Va/V2
// kept per column with incremental updates; horizontal kz-window sums slide
// in registers; the kz-1 halo columns come from lane+1 via shfl.
template <int KZ, int W, int CPT, int CH>
__device__ __forceinline__ float strip_residual(const float* __restrict__ plane,
                                                int i0, int lane) {
    constexpr int   HOUT  = W - KZ + 1;
    constexpr int   HW    = CPT + KZ - 1;
    constexpr float m     = (KZ - 1) * 0.5f;
    constexpr float invD1 = 12.0f / (float)(KZ * KZ * (KZ * KZ - 1));
    constexpr float invD0 = 1.0f / (float)(KZ * KZ);

    const int col0 = lane * CPT;
    const float* __restrict__ p = plane + (size_t)i0 * W + col0;

    // Rolling register window of KZ input rows x CPT columns.
    float r[KZ][CPT];
#pragma unroll
    for (int a = 0; a < KZ; ++a)
#pragma unroll
        for (int v = 0; v < CPT / 4; ++v) {
            float4 t = *reinterpret_cast<const float4*>(p + (size_t)a * W + v * 4);
            r[a][v * 4 + 0] = t.x; r[a][v * 4 + 1] = t.y;
            r[a][v * 4 + 2] = t.z; r[a][v * 4 + 3] = t.w;
        }

    // Initial vertical sums.
    float V0[CPT], Va[CPT], V2[CPT];
#pragma unroll
    for (int c = 0; c < CPT; ++c) {
        float s0 = 0.f, sa = 0.f, s2 = 0.f;
#pragma unroll
        for (int a = 0; a < KZ; ++a) {
            s0 += r[a][c];
            sa += ((float)a - m) * r[a][c];
            s2 += r[a][c] * r[a][c];
        }
        V0[c] = s0; Va[c] = sa; V2[c] = s2;
    }

    float partial = 0.f;

    for (int base = 0; base < CH; base += KZ) {
#pragma unroll
        for (int s = 0; s < KZ; ++s) {
            const int ii = base + s;
            if (ii >= CH) break;

            // Assemble own + halo vertical sums (halo from lane+1; lane 31's
            // halo is garbage-but-finite and only feeds predicated-off outputs).
            float h0[HW], ha[HW], h2[HW];
#pragma unroll
            for (int c = 0; c < CPT; ++c) { h0[c] = V0[c]; ha[c] = Va[c]; h2[c] = V2[c]; }
#pragma unroll
            for (int k = 0; k < KZ - 1; ++k) {
                h0[CPT + k] = __shfl_down_sync(0xffffffffu, V0[k], 1);
                ha[CPT + k] = __shfl_down_sync(0xffffffffu, Va[k], 1);
                h2[CPT + k] = __shfl_down_sync(0xffffffffu, V2[k], 1);
            }

            // First horizontal window, then slide.
            float S0 = 0.f, Sa = 0.f, Sc = 0.f, S2 = 0.f;
#pragma unroll
            for (int c = 0; c < KZ; ++c) {
                S0 += h0[c];
                Sc += ((float)c - m) * h0[c];
                Sa += ha[c];
                S2 += h2[c];
            }
#pragma unroll
            for (int j = 0; j < CPT; ++j) {
                if (col0 + j < HOUT)
                    partial += S2 - (Sa * Sa + Sc * Sc) * invD1 - S0 * S0 * invD0;
                if (j + 1 < CPT) {
                    const float d0 = h0[j], dn = h0[j + KZ];
                    Sc = Sc - S0 + (m + 1.f) * d0 + m * dn;   // uses old S0
                    S0 += dn - d0;
                    Sa += ha[j + KZ] - ha[j];
                    S2 += h2[j + KZ] - h2[j];
                }
            }

            // Vertical slide: drop row in slot s, load next input row into it.
            if (ii + 1 < CH) {
                const float* pn = p + (size_t)(ii + KZ) * W;
#pragma unroll
                for (int v = 0; v < CPT / 4; ++v) {
                    float4 t = *reinterpret_cast<const float4*>(pn + v * 4);
                    float gn[4] = {t.x, t.y, t.z, t.w};
#pragma unroll
                    for (int q = 0; q < 4; ++q) {
                        const int c = v * 4 + q;
                        const float gd = r[s][c];
                        Va[c] = Va[c] - V0[c] + (m + 1.f) * gd + m * gn[q]; // old V0
                        V0[c] += gn[q] - gd;
                        V2[c] = V2[c] + gn[q] * gn[q] - gd * gd;
                        r[s][c] = gn[q];
                    }
                }
            }
        }
    }
    return partial;
}

// 128 blocks x 16 warps. Warps 0..8: flow1 (kz=5, 18 chunks of 14 rows per
// plane); warps 9..15: flow0 (kz=3, 14 chunks of 9 rows). 128*9=1152=64*18,
// 128*7=896=64*14 -> exact cover, every block has identical work (balanced wave).
__global__ __launch_bounds__(512, 1)
void fused_loss_kernel(const float* __restrict__ f0,
                       const float* __restrict__ f1,
                       float* __restrict__ out) {
    const int wid  = threadIdx.x >> 5;
    const int lane = threadIdx.x & 31;

    float partial;
    if (wid < 9) {
        const int idx   = blockIdx.x * 9 + wid;          // 0..1151
        const int plane = idx / 18, chunk = idx % 18;
        partial = strip_residual<5, 256, 8, 14>(f1 + (size_t)plane * 256 * 256,
                                                chunk * 14, lane);
    } else {
        const int idx   = blockIdx.x * 7 + (wid - 9);    // 0..895
        const int plane = idx / 14, chunk = idx % 14;
        partial = strip_residual<3, 128, 4, 9>(f0 + (size_t)plane * 128 * 128,
                                               chunk * 9, lane);
    }

#pragma unroll
    for (int off = 16; off > 0; off >>= 1)
        partial += __shfl_down_sync(0xffffffffu, partial, off);

    __shared__ double sh[16];
    if (lane == 0) sh[wid] = (double)partial;
    __syncthreads();

    if (threadIdx.x == 0) {
        double a1 = 0.0, a0 = 0.0;
#pragma unroll
        for (int w = 0; w < 9; ++w)  a1 += sh[w];
#pragma unroll
        for (int w = 9; w < 16; ++w) a0 += sh[w];
        atomicAdd(&g_acc[0], a0);
        atomicAdd(&g_acc[1], a1);
        __threadfence();
        const unsigned done = atomicAdd(&g_cnt, 1);
        if (done == gridDim.x - 1) {          // last block: finalize + reset
            __threadfence();
            const double r0 = g_acc[0], r1 = g_acc[1];
            out[0] = (float)(r0 / (32.0 * 126.0 * 126.0) +
                             r1 / (32.0 * 252.0 * 252.0));
            g_acc[0] = 0.0; g_acc[1] = 0.0; g_cnt = 0u;
        }
    }
}

extern "C" void kernel_launch(void* const* d_in, const int* in_sizes, int n_in,
                              void* d_out, int out_size) {
    const float* flow0 = (const float*)d_in[0];  // (32, 2, 128, 128)
    const float* flow1 = (const float*)d_in[1];  // (32, 2, 256, 256)
    if (n_in >= 2 && in_sizes[0] > in_sizes[1]) {
        const float* t = flow0; flow0 = flow1; flow1 = t;
    }
    fused_loss_kernel<<<128, 512>>>(flow0, flow1, (float*)d_out);
}

// round 3
// speedup vs baseline: 2.0108x; 1.0172x over previous
#include <cuda_runtime.h>

__device__ double   g_acc[2];   // [0]=flow0 (kz=3), [1]=flow1 (kz=5)
__device__ unsigned g_cnt = 0;

// Warp-strip separable affine residual:
//   res(pixel) = S2 - (Sa^2 + Sc^2)/D1 - S0^2/D0  ( == p^T K^T K p; the
// coordinate grids are affine in patch offsets, annihilated by I-P).
// Vertical kz-window sums V0/Va/V2 per column, updated incrementally; the
// dropped row is either kept in registers (KEEP=true, cheap for kz=3) or
// reloaded from L1 (KEEP=false, saves (KZ-1)*CPT regs for kz=5).
// Horizontal kz-window slides in registers; halo columns come from lane+1 shfl.
template <int KZ, int W, int CPT, int CH, bool KEEP>
__device__ __forceinline__ float strip_residual(const float* __restrict__ plane,
                                                int i0, int lane) {
    constexpr int   HOUT  = W - KZ + 1;
    constexpr int   HW    = CPT + KZ - 1;
    constexpr float m     = (KZ - 1) * 0.5f;
    constexpr float invD1 = 12.0f / (float)(KZ * KZ * (KZ * KZ - 1));
    constexpr float invD0 = 1.0f / (float)(KZ * KZ);

    const int col0 = lane * CPT;
    const float* __restrict__ p = plane + (size_t)i0 * W + col0;

    float r[KZ][CPT];          // only touched when KEEP (else eliminated)
    float V0[CPT], Va[CPT], V2[CPT];
#pragma unroll
    for (int c = 0; c < CPT; ++c) { V0[c] = 0.f; Va[c] = 0.f; V2[c] = 0.f; }

    // Initial vertical sums over rows i0..i0+KZ-1.
#pragma unroll
    for (int a = 0; a < KZ; ++a) {
#pragma unroll
        for (int v = 0; v < CPT / 4; ++v) {
            float4 t = *reinterpret_cast<const float4*>(p + (size_t)a * W + v * 4);
            float g4[4] = {t.x, t.y, t.z, t.w};
#pragma unroll
            for (int q = 0; q < 4; ++q) {
                const int c = v * 4 + q;
                const float g = g4[q];
                V0[c] += g;
                Va[c] += ((float)a - m) * g;
                V2[c] += g * g;
                if (KEEP) r[a][c] = g;
            }
        }
    }

    float partial = 0.f;

#pragma unroll 3
    for (int ii = 0; ii < CH; ++ii) {
        // Halo vertical sums from lane+1 (lane 31's halo is its own value:
        // finite garbage feeding only predicated-off outputs).
        float h0[HW], ha[HW], h2[HW];
#pragma unroll
        for (int c = 0; c < CPT; ++c) { h0[c] = V0[c]; ha[c] = Va[c]; h2[c] = V2[c]; }
#pragma unroll
        for (int k = 0; k < KZ - 1; ++k) {
            h0[CPT + k] = __shfl_down_sync(0xffffffffu, V0[k], 1);
            ha[CPT + k] = __shfl_down_sync(0xffffffffu, Va[k], 1);
            h2[CPT + k] = __shfl_down_sync(0xffffffffu, V2[k], 1);
        }

        // First horizontal window, then slide across CPT outputs.
        float S0 = 0.f, Sa = 0.f, Sc = 0.f, S2 = 0.f;
#pragma unroll
        for (int c = 0; c < KZ; ++c) {
            S0 += h0[c];
            Sc += ((float)c - m) * h0[c];
            Sa += ha[c];
            S2 += h2[c];
        }
#pragma unroll
        for (int j = 0; j < CPT; ++j) {
            if (col0 + j < HOUT)
                partial += S2 - (Sa * Sa + Sc * Sc) * invD1 - S0 * S0 * invD0;
            if (j + 1 < CPT) {
                const float d0 = h0[j], dn = h0[j + KZ];
                Sc = Sc - S0 + (m + 1.f) * d0 + m * dn;   // uses old S0
                S0 += dn - d0;
                Sa += ha[j + KZ] - ha[j];
                S2 += h2[j + KZ] - h2[j];
            }
        }

        // Vertical slide: subtract row ii, add row ii+KZ.
        if (ii + 1 < CH) {
            const float* pn = p + (size_t)(ii + KZ) * W;
            const float* po = p + (size_t)ii * W;       // L1-resident reload
#pragma unroll
            for (int v = 0; v < CPT / 4; ++v) {
                float4 tn = *reinterpret_cast<const float4*>(pn + v * 4);
                float gn4[4] = {tn.x, tn.y, tn.z, tn.w};
                float gd4[4];
                if (KEEP) {
#pragma unroll
                    for (int q = 0; q < 4; ++q) gd4[q] = r[ii % KZ][v * 4 + q];
                } else {
                    float4 to = *reinterpret_cast<const float4*>(po + v * 4);
                    gd4[0] = to.x; gd4[1] = to.y; gd4[2] = to.z; gd4[3] = to.w;
                }
#pragma unroll
                for (int q = 0; q < 4; ++q) {
                    const int c = v * 4 + q;
                    const float gd = gd4[q], gn = gn4[q];
                    Va[c] = Va[c] - V0[c] + (m + 1.f) * gd + m * gn;  // old V0
                    V0[c] += gn - gd;
                    V2[c] = V2[c] + gn * gn - gd * gd;
                    if (KEEP) r[ii % KZ][c] = gn;
                }
            }
        }
    }
    return partial;
}

// 336 blocks x 8 warps = 2688 independent warp-tasks.
//   heavy (kz=5): 64 planes x 28 chunks of 9 rows = 1792 tasks
//   light (kz=3): 64 planes x 14 chunks of 9 rows =  896 tasks
// Interleave H,H,L via t%3 so every block carries an identical cost mix;
// with 3 blocks/SM resident the whole grid is one balanced wave.
__global__ __launch_bounds__(256, 3)
void fused_loss_kernel(const float* __restrict__ f0,
                       const float* __restrict__ f1,
                       float* __restrict__ out) {
    const int wid  = threadIdx.x >> 5;
    const int lane = threadIdx.x & 31;
    const int t    = blockIdx.x * 8 + wid;      // 0..2687
    const int tm   = t % 3;

    float partial;
    int   which;
    if (tm < 2) {                               // heavy: kz=5 on flow1
        const int h     = (t / 3) * 2 + tm;     // 0..1791
        const int plane = h / 28, chunk = h % 28;
        partial = strip_residual<5, 256, 8, 9, false>(
            f1 + (size_t)plane * 256 * 256, chunk * 9, lane);
        which = 1;
    } else {                                    // light: kz=3 on flow0
        const int l     = t / 3;                // 0..895
        const int plane = l / 14, chunk = l % 14;
        partial = strip_residual<3, 128, 4, 9, true>(
            f0 + (size_t)plane * 128 * 128, chunk * 9, lane);
        which = 0;
    }

#pragma unroll
    for (int off = 16; off > 0; off >>= 1)
        partial += __shfl_down_sync(0xffffffffu, partial, off);

    __shared__ double sh[8];
    __shared__ int    shw[8];
    if (lane == 0) { sh[wid] = (double)partial; shw[wid] = which; }
    __syncthreads();

    if (threadIdx.x == 0) {
        double a0 = 0.0, a1 = 0.0;
#pragma unroll
        for (int w = 0; w < 8; ++w) {
            if (shw[w]) a1 += sh[w]; else a0 += sh[w];
        }
        atomicAdd(&g_acc[0], a0);
        atomicAdd(&g_acc[1], a1);
        __threadfence();
        const unsigned done = atomicAdd(&g_cnt, 1);
        if (done == gridDim.x - 1) {            // last block: finalize + reset
            __threadfence();
            const double r0 = g_acc[0], r1 = g_acc[1];
            out[0] = (float)(r0 / (32.0 * 126.0 * 126.0) +
                             r1 / (32.0 * 252.0 * 252.0));
            g_acc[0] = 0.0; g_acc[1] = 0.0; g_cnt = 0u;
        }
    }
}

extern "C" void kernel_launch(void* const* d_in, const int* in_sizes, int n_in,
                              void* d_out, int out_size) {
    const float* flow0 = (const float*)d_in[0];  // (32, 2, 128, 128)
    const float* flow1 = (const float*)d_in[1];  // (32, 2, 256, 256)
    if (n_in >= 2 && in_sizes[0] > in_sizes[1]) {
        const float* t = flow0; flow0 = flow1; flow1 = t;
    }
    fused_loss_kernel<<<336, 256>>>(flow0, flow1, (float*)d_out);
}